// round 6
// baseline (speedup 1.0000x reference)
#include <cuda_runtime.h>

// Bilateral filter 9x9, sigma_s=3, sigma_r=0.1, reflect padding, 4096x4096 fp32.
//
// w = exp2( Ls(dx,dy) - K2*(win-c)^2 ),  K2 = 50*log2(e)
// expanded: arg = (-K2*win + a)*win + (b + Ls),  a = 2*K2*c, b = -K2*c^2
//
// Round-6: scalar structure (R1/R5 lineage), vertical register reuse deepened
// to 4 pixels/thread: each window row's 9 floats are loaded into registers
// once and feed 4 pixels -> LDS/px 45 -> 27; fill/epilogue amortized 4x.
// 8 independent accumulator chains provide ILP at ~50% occupancy.

#define IMG_H 4096
#define IMG_W 4096
#define RAD 4
#define BX 32
#define BY 8
#define PY 4                       // vertical pixels per thread
#define TILE_PH (BY * PY)          // 32 pixel rows per block
#define TW (BX + 2*RAD)            // 40
#define TH (TILE_PH + 2*RAD)       // 40

__device__ __forceinline__ float ex2f(float x) {
    float y;
    asm("ex2.approx.f32 %0, %1;" : "=f"(y) : "f"(x));
    return y;
}

__global__ __launch_bounds__(BX * BY)
void bilateral_kernel(const float* __restrict__ img, float* __restrict__ out) {
    __shared__ float tile[TH][TW];

    const int tx = threadIdx.x;
    const int ty = threadIdx.y;
    const int bx0 = blockIdx.x * BX;
    const int by0 = blockIdx.y * TILE_PH;

    // ---- tile fill: warp-per-row strided, no division, reflect at edges ----
    #pragma unroll
    for (int r = ty; r < TH; r += BY) {
        int gy = by0 + r - RAD;
        gy = (gy < 0) ? -gy : ((gy >= IMG_H) ? (2 * IMG_H - 2 - gy) : gy);
        const float* __restrict__ src = img + (size_t)gy * IMG_W;
        #pragma unroll
        for (int c = tx; c < TW; c += BX) {
            int gx = bx0 + c - RAD;
            gx = (gx < 0) ? -gx : ((gx >= IMG_W) ? (2 * IMG_W - 2 - gx) : gx);
            tile[r][c] = src[gx];
        }
    }
    __syncthreads();

    const float K2 = 72.13475204444817f;                   // 50 * log2(e)
    const float LOG2E_OVER_S = 1.4426950408889634f / 18.0f;

    // this thread's four pixels: tile rows py0 .. py0+3
    const int py0 = ty * PY;

    float a[PY], b[PY], num[PY], den[PY];
    #pragma unroll
    for (int j = 0; j < PY; j++) {
        const float c = tile[py0 + RAD + j][tx + RAD];
        a[j] = 2.0f * K2 * c;
        b[j] = -K2 * c * c;
        num[j] = 0.f;
        den[j] = 0.f;
    }

    // window rows 0..11 relative to py0: row r serves pixel j iff j<=r<=j+8
    #pragma unroll
    for (int r = 0; r < PY + 8; r++) {
        float f[9];
        #pragma unroll
        for (int k = 0; k < 9; k++) f[k] = tile[py0 + r][tx + k];

        #pragma unroll
        for (int j = 0; j < PY; j++) {
            if (r >= j && r <= j + 8) {
                const int dyq = (r - j - 4) * (r - j - 4);   // compile-time
                #pragma unroll
                for (int k = 0; k < 9; k++) {
                    const float win = f[k];
                    const float Ls = -(float)((k - 4) * (k - 4) + dyq) * LOG2E_OVER_S;
                    const float btap = b[j] + Ls;            // CSE'd per pixel
                    const float t   = fmaf(-K2, win, a[j]);  // FFMA-imm (rt=1)
                    const float arg = fmaf(win, t, btap);
                    const float w   = ex2f(arg);             // MUFU.EX2
                    num[j] = fmaf(w, win, num[j]);
                    den[j] += w;
                }
            }
        }
    }

    size_t o = (size_t)(by0 + py0) * IMG_W + bx0 + tx;
    #pragma unroll
    for (int j = 0; j < PY; j++) {
        out[o] = __fdividef(num[j], den[j]);
        o += IMG_W;
    }
}

extern "C" void kernel_launch(void* const* d_in, const int* in_sizes, int n_in,
                              void* d_out, int out_size) {
    const float* img = (const float*)d_in[0];
    float* out = (float*)d_out;
    dim3 block(BX, BY);
    dim3 grid(IMG_W / BX, IMG_H / TILE_PH);
    bilateral_kernel<<<grid, block>>>(img, out);
}

// round 7
// speedup vs baseline: 1.0002x; 1.0002x over previous
#include <cuda_runtime.h>

// Bilateral filter 9x9, sigma_s=3, sigma_r=0.1, reflect padding, 4096x4096 fp32.
//
// w = exp2( Ls(dx,dy) - K2*(win-c)^2 ),  K2 = 50*log2(e)
// expanded: arg = (-K2*win + a)*win + (b + Ls),  a = 2*K2*c, b = -K2*c^2
//
// Round-7: 2x2 pixels/thread. Window rows loaded as float2 (LDS.64, halves
// consumed as scalars -> no marshalling) and shared by all 4 pixels:
// LDS/px 45 -> 12.5. Tap math stays the proven 5-issue scalar form.
// Regs capped at 51 (5 blocks/SM, 62.5% occ) to stay on the issue-eff knee.

#define IMG_H 4096
#define IMG_W 4096
#define RAD 4
#define BX 32
#define BY 8
#define PX 2
#define PY 2
#define TILE_PW (BX * PX)          // 64 pixel cols per block
#define TILE_PH (BY * PY)          // 16 pixel rows per block
#define TW (TILE_PW + 2*RAD)       // 72 floats per tile row (288B, 8B-aligned)
#define TH (TILE_PH + 2*RAD)       // 24 rows

__device__ __forceinline__ float ex2f(float x) {
    float y;
    asm("ex2.approx.f32 %0, %1;" : "=f"(y) : "f"(x));
    return y;
}

__global__ __launch_bounds__(BX * BY, 5)
void bilateral_kernel(const float* __restrict__ img, float* __restrict__ out) {
    __shared__ __align__(16) float tile[TH][TW];

    const int tx = threadIdx.x;
    const int ty = threadIdx.y;
    const int bx0 = blockIdx.x * TILE_PW;
    const int by0 = blockIdx.y * TILE_PH;

    // ---- tile fill: warp-per-row strided, reflect at edges ----
    #pragma unroll
    for (int r = ty; r < TH; r += BY) {
        int gy = by0 + r - RAD;
        gy = (gy < 0) ? -gy : ((gy >= IMG_H) ? (2 * IMG_H - 2 - gy) : gy);
        const float* __restrict__ src = img + (size_t)gy * IMG_W;
        #pragma unroll
        for (int c = tx; c < TW; c += BX) {
            int gx = bx0 + c - RAD;
            gx = (gx < 0) ? -gx : ((gx >= IMG_W) ? (2 * IMG_W - 2 - gx) : gx);
            tile[r][c] = src[gx];
        }
    }
    __syncthreads();

    const float K2 = 72.13475204444817f;                   // 50 * log2(e)
    const float LOG2E_OVER_S = 1.4426950408889634f / 18.0f;

    const int cb  = tx * PX;   // window col base (even -> float2 aligned)
    const int py0 = ty * PY;   // window row base

    // 4 pixels: (row j, col i), centers tile[py0+4+j][cb+4+i]
    float a[4], b[4], num[4], den[4];
    #pragma unroll
    for (int j = 0; j < PY; j++) {
        #pragma unroll
        for (int i = 0; i < PX; i++) {
            const float c = tile[py0 + RAD + j][cb + RAD + i];
            a[j * 2 + i] = 2.0f * K2 * c;
            b[j * 2 + i] = -K2 * c * c;
            num[j * 2 + i] = 0.f;
            den[j * 2 + i] = 0.f;
        }
    }

    // window rows 0..9 relative to py0; row r serves pixel-row j iff j<=r<=j+8
    #pragma unroll
    for (int r = 0; r < PY + 8; r++) {
        // load the 10-wide union row as 5 aligned LDS.64; halves used as scalars
        float f[10];
        const float2* __restrict__ rp =
            reinterpret_cast<const float2*>(&tile[py0 + r][cb]);
        #pragma unroll
        for (int q = 0; q < 5; q++) {
            const float2 v = rp[q];
            f[2 * q]     = v.x;
            f[2 * q + 1] = v.y;
        }

        #pragma unroll
        for (int j = 0; j < PY; j++) {
            if (r >= j && r <= j + 8) {
                const int dyq = (r - j - 4) * (r - j - 4);   // compile-time
                #pragma unroll
                for (int i = 0; i < PX; i++) {
                    const int p = j * 2 + i;
                    #pragma unroll
                    for (int k = 0; k < 9; k++) {
                        const float win = f[i + k];
                        const float Ls = -(float)((k - 4) * (k - 4) + dyq)
                                         * LOG2E_OVER_S;
                        const float btap = b[p] + Ls;          // CSE'd per pixel
                        const float t   = fmaf(-K2, win, a[p]); // FFMA-imm
                        const float arg = fmaf(win, t, btap);
                        const float w   = ex2f(arg);            // MUFU.EX2
                        num[p] = fmaf(w, win, num[p]);
                        den[p] += w;
                    }
                }
            }
        }
    }

    // 2x2 output, each row as one aligned 8B store
    #pragma unroll
    for (int j = 0; j < PY; j++) {
        float2 o;
        o.x = __fdividef(num[j * 2 + 0], den[j * 2 + 0]);
        o.y = __fdividef(num[j * 2 + 1], den[j * 2 + 1]);
        *reinterpret_cast<float2*>(
            &out[(size_t)(by0 + py0 + j) * IMG_W + bx0 + cb]) = o;
    }
}

extern "C" void kernel_launch(void* const* d_in, const int* in_sizes, int n_in,
                              void* d_out, int out_size) {
    const float* img = (const float*)d_in[0];
    float* out = (float*)d_out;
    dim3 block(BX, BY);
    dim3 grid(IMG_W / TILE_PW, IMG_H / TILE_PH);
    bilateral_kernel<<<grid, block>>>(img, out);
}

// round 8
// speedup vs baseline: 1.1067x; 1.1065x over previous
#include <cuda_runtime.h>
#include <cuda_fp16.h>

// Bilateral filter 9x9, sigma_s=3, sigma_r=0.1, reflect padding, 4096x4096 fp32.
//
// w = exp2( Ls(dx,dy) - K2*(win-c)^2 ),  K2 = 50*log2(e)
// expanded: arg = (-K2*win + a)*win + (b + Ls),  a = 2*K2*c, b = -K2*c^2
//
// Round-8: R5 geometry (2 vertical pixels/thread, scalar window regs, best
// kernel so far), but the two pixels' exp2 at each shared (row,k) tap are
// PACKED into one ex2.approx.f16x2 -> MUFU ops/px drop 81 -> 45.
// Args computed and accumulated in f32 (precision); only the exp2 input is
// rounded to f16 (weight rel-err ~1e-4..7e-4, cancels in num/den ratio).

#define IMG_H 4096
#define IMG_W 4096
#define RAD 4
#define BX 32
#define BY 8
#define PY 2
#define TILE_PH (BY * PY)          // 16
#define TW (BX + 2*RAD)            // 40
#define TH (TILE_PH + 2*RAD)       // 24

__device__ __forceinline__ float ex2f(float x) {
    float y;
    asm("ex2.approx.f32 %0, %1;" : "=f"(y) : "f"(x));
    return y;
}

// one MUFU op, two exp2's
__device__ __forceinline__ float2 ex2pair(float a0, float a1) {
    __half2 h = __floats2half2_rn(a0, a1);
    unsigned hu = *reinterpret_cast<unsigned*>(&h);
    unsigned wu;
    asm("ex2.approx.f16x2 %0, %1;" : "=r"(wu) : "r"(hu));
    __half2 w = *reinterpret_cast<__half2*>(&wu);
    return make_float2(__low2float(w), __high2float(w));
}

__global__ __launch_bounds__(BX * BY, 4)
void bilateral_kernel(const float* __restrict__ img, float* __restrict__ out) {
    __shared__ float tile[TH][TW];

    const int tx = threadIdx.x;
    const int ty = threadIdx.y;
    const int bx0 = blockIdx.x * BX;
    const int by0 = blockIdx.y * TILE_PH;

    // ---- tile fill: warp-per-row strided, reflect at edges ----
    #pragma unroll
    for (int r = ty; r < TH; r += BY) {
        int gy = by0 + r - RAD;
        gy = (gy < 0) ? -gy : ((gy >= IMG_H) ? (2 * IMG_H - 2 - gy) : gy);
        const float* __restrict__ src = img + (size_t)gy * IMG_W;
        #pragma unroll
        for (int c = tx; c < TW; c += BX) {
            int gx = bx0 + c - RAD;
            gx = (gx < 0) ? -gx : ((gx >= IMG_W) ? (2 * IMG_W - 2 - gx) : gx);
            tile[r][c] = src[gx];
        }
    }
    __syncthreads();

    const float K2 = 72.13475204444817f;                   // 50 * log2(e)
    const float LOG2E_OVER_S = 1.4426950408889634f / 18.0f;

    const int py0 = ty * PY;

    const float c0 = tile[py0 + RAD][tx + RAD];
    const float c1 = tile[py0 + RAD + 1][tx + RAD];
    const float a0 = 2.0f * K2 * c0, b0 = -K2 * c0 * c0;
    const float a1 = 2.0f * K2 * c1, b1 = -K2 * c1 * c1;

    float num0 = 0.f, den0 = 0.f;
    float num1 = 0.f, den1 = 0.f;

    // window rows 0..9: row 0 -> px0 only, row 9 -> px1 only, rows 1..8 both.
    #pragma unroll
    for (int r = 0; r < 10; r++) {
        float f[9];
        #pragma unroll
        for (int k = 0; k < 9; k++) f[k] = tile[py0 + r][tx + k];

        if (r == 0) {
            // px0 only, scalar f32 ex2 (9 taps)
            #pragma unroll
            for (int k = 0; k < 9; k++) {
                const float win = f[k];
                const float Ls = -(float)((k - 4) * (k - 4) + 16) * LOG2E_OVER_S;
                const float t   = fmaf(-K2, win, a0);
                const float arg = fmaf(win, t, b0 + Ls);
                const float w   = ex2f(arg);
                num0 = fmaf(w, win, num0);
                den0 += w;
            }
        } else if (r == 9) {
            // px1 only, scalar f32 ex2 (9 taps)
            #pragma unroll
            for (int k = 0; k < 9; k++) {
                const float win = f[k];
                const float Ls = -(float)((k - 4) * (k - 4) + 16) * LOG2E_OVER_S;
                const float t   = fmaf(-K2, win, a1);
                const float arg = fmaf(win, t, b1 + Ls);
                const float w   = ex2f(arg);
                num1 = fmaf(w, win, num1);
                den1 += w;
            }
        } else {
            // both pixels share win=f[k]; one f16x2 ex2 serves both
            const int dq0 = (r - 4) * (r - 4);   // px0 row offset^2 (compile-time)
            const int dq1 = (r - 5) * (r - 5);   // px1
            #pragma unroll
            for (int k = 0; k < 9; k++) {
                const float win = f[k];
                const int   kq  = (k - 4) * (k - 4);
                const float Ls0 = -(float)(kq + dq0) * LOG2E_OVER_S;
                const float Ls1 = -(float)(kq + dq1) * LOG2E_OVER_S;
                const float t0   = fmaf(-K2, win, a0);
                const float arg0 = fmaf(win, t0, b0 + Ls0);  // b+Ls CSE'd
                const float t1   = fmaf(-K2, win, a1);
                const float arg1 = fmaf(win, t1, b1 + Ls1);
                const float2 w   = ex2pair(arg0, arg1);      // ONE MUFU
                num0 = fmaf(w.x, win, num0);
                den0 += w.x;
                num1 = fmaf(w.y, win, num1);
                den1 += w.y;
            }
        }
    }

    const size_t o0 = (size_t)(by0 + py0) * IMG_W + bx0 + tx;
    out[o0]         = __fdividef(num0, den0);
    out[o0 + IMG_W] = __fdividef(num1, den1);
}

extern "C" void kernel_launch(void* const* d_in, const int* in_sizes, int n_in,
                              void* d_out, int out_size) {
    const float* img = (const float*)d_in[0];
    float* out = (float*)d_out;
    dim3 block(BX, BY);
    dim3 grid(IMG_W / BX, IMG_H / TILE_PH);
    bilateral_kernel<<<grid, block>>>(img, out);
}